// round 14
// baseline (speedup 1.0000x reference)
#include <cuda_runtime.h>
#include <cuda_bf16.h>

#define LMAX 13
#define LPAD 14
#define NP 7          // f32x2 pairs per padded row (LPAD/2)
#define N_TYPES 20
#define NRES_MAX 2048
#define DV 64
#define TPB 192       // = DV * 3
#define HROWS 7       // max rows per half-block = ceil(13/2)

typedef unsigned long long u64;

// packed f32x2 fma: acc = w * dv + acc   (2 scalar FMAs in 1 issue slot)
#define FMA2(acc, w, dv) \
    asm("fma.rn.f32x2 %0, %1, %2, %3;" : "=l"(acc) : "l"(w), "l"(dv), "l"(acc))

// horizontal sum of a packed f32x2
__device__ __forceinline__ float hsum2(u64 v) {
    float lo, hi;
    asm("mov.b64 {%0, %1}, %2;" : "=f"(lo), "=f"(hi) : "l"(v));
    return lo + hi;
}

__constant__ int c_res_len[N_TYPES] = {3,4,5,5,6,6,6,7,7,7,7,7,8,8,8,9,10,10,11,13};
__device__ int g_starts[NRES_MAX];

// padded weights, built once per launch by prep_kernel
__device__ float g_Wpad_atm[N_TYPES * LMAX * DV * LPAD];  // [t][m][v][14], slot13=0
__device__ float g_Wpad_amn[N_TYPES * DV * LPAD];         // [t][v][14],    slot13=0

// ---------------------------------------------------------------------------
// Kernel 0: fused prep. Block 0: exclusive scan of residue lengths.
// Blocks 1..: pad W_atm / W_amn rows 13 -> 14 (zero slot 13).
// ---------------------------------------------------------------------------
__global__ __launch_bounds__(1024) void prep_kernel(
    const int* __restrict__ seq, int n_res,
    const float* __restrict__ W_amn, const float* __restrict__ W_atm)
{
    if (blockIdx.x == 0) {
        __shared__ int s[1024];
        int tid = threadIdx.x;
        int i0 = 2 * tid, i1 = 2 * tid + 1;
        int l0 = (i0 < n_res) ? c_res_len[seq[i0]] : 0;
        int l1 = (i1 < n_res) ? c_res_len[seq[i1]] : 0;
        int pair = l0 + l1;
        s[tid] = pair;
        __syncthreads();
        #pragma unroll
        for (int off = 1; off < 1024; off <<= 1) {
            int v = (tid >= off) ? s[tid - off] : 0;
            __syncthreads();
            s[tid] += v;
            __syncthreads();
        }
        int excl = s[tid] - pair;
        if (i0 < n_res) g_starts[i0] = excl;
        if (i1 < n_res) g_starts[i1] = excl + l0;
    } else {
        const int NATM = N_TYPES * LMAX * DV;
        const int NAMN = N_TYPES * DV;
        int idx = (blockIdx.x - 1) * 1024 + threadIdx.x;
        if (idx < NATM * LPAD) {
            int row = idx / LPAD, l = idx - row * LPAD;
            g_Wpad_atm[idx] = (l < LMAX) ? W_atm[row * LMAX + l] : 0.0f;
        } else {
            int j = idx - NATM * LPAD;
            if (j < NAMN * LPAD) {
                int row = j / LPAD, l = j - row * LPAD;
                g_Wpad_amn[j] = (l < LMAX) ? W_amn[row * LMAX + l] : 0.0f;
            }
        }
    }
}

// ---------------------------------------------------------------------------
// Templated hot path. L compile-time; BB = batch-block factor (4 for small
// NPL, 2 for large NPL to keep regs under the 5-blocks/SM budget).
// m_count is runtime (this block's half of the atoms).
// ---------------------------------------------------------------------------
template<int L, int BB>
__device__ __forceinline__ void posmix_body(
    const u64* __restrict__ sW64v,     // shared W base for this thread's v
    const u64* __restrict__ sd64d,     // shared diff base for this thread's d
    const u64* __restrict__ gWa64,     // padded W_amn row for (t, v)
    float* __restrict__ qamn,
    float* __restrict__ patm,
    int B, int bstride_amn, int bstride_atm,
    int m_count, bool do_amn)
{
    constexpr int NPL = (L + 1) / 2;   // f32x2 pairs covering L (diff zero-padded)

    #pragma unroll 1
    for (int bb0 = 0; bb0 < B; bb0 += BB) {
        u64 dv[BB][NPL];
        #pragma unroll
        for (int b = 0; b < BB; b++)
            #pragma unroll
            for (int p = 0; p < NPL; p++)
                dv[b][p] = sd64d[(bb0 + b) * 3 * NP + p];

        // ---- x_v_amn (half-0 blocks only) ----
        if (do_amn) {
            u64 c[BB];
            #pragma unroll
            for (int b = 0; b < BB; b++) c[b] = 0;
            #pragma unroll
            for (int p = 0; p < NPL; p++) {
                u64 w = gWa64[p];
                #pragma unroll
                for (int b = 0; b < BB; b++) FMA2(c[b], w, dv[b][p]);
            }
            #pragma unroll
            for (int b = 0; b < BB; b++)
                qamn[(size_t)(bb0 + b) * bstride_amn] = hsum2(c[b]);
        }

        // ---- x_v_atm : dynamic m-loop over this block's half ----
        float* pp[BB];
        #pragma unroll
        for (int b = 0; b < BB; b++)
            pp[b] = patm + (size_t)(bb0 + b) * bstride_atm;
        const u64* wr = sW64v;
        #pragma unroll 1
        for (int m = 0; m < m_count; m++) {
            u64 c[BB];
            #pragma unroll
            for (int b = 0; b < BB; b++) c[b] = 0;
            #pragma unroll
            for (int p = 0; p < NPL; p++) {
                u64 w = wr[p];
                #pragma unroll
                for (int b = 0; b < BB; b++) FMA2(c[b], w, dv[b][p]);
            }
            #pragma unroll
            for (int b = 0; b < BB; b++) {
                pp[b][0] = hsum2(c[b]);
                pp[b] += DV * 3;
            }
            wr += DV * NP;
        }
    }
}

// ---------------------------------------------------------------------------
// Kernel 2: fused gather + dual-einsum + scatter.
// TWO blocks per residue (atom-halves) -> smaller smem (5 blocks/SM).
// ---------------------------------------------------------------------------
__global__ __launch_bounds__(TPB, 5) void posmix_kernel(
    const float* __restrict__ pos_atm,   // (B, atoms, 3)
    const float* __restrict__ pos_amn,   // (B, n_res, 3)
    const int*   __restrict__ seq,       // (n_res,)
    float* __restrict__ out_atm,         // (B, atoms, 64, 3)
    float* __restrict__ out_amn,         // (B, n_res, 64, 3)
    int B, int n_res, int atoms)
{
    extern __shared__ float smem[];
    float* sW    = smem;                        // HROWS*DV*LPAD = 6272 floats
    float* sdiff = smem + HROWS * DV * LPAD;    // B*3*LPAD     =  672 floats

    const int rid  = blockIdx.x >> 1;
    const int half = blockIdx.x & 1;
    const int tid  = threadIdx.x;
    const int t    = seq[rid];
    const int L    = c_res_len[t];
    const int start = g_starts[rid];

    const int h1      = (L + 1) >> 1;
    const int m_begin = half ? h1 : 0;
    const int m_count = half ? (L - h1) : h1;

    // --- stage this half's pre-padded W_atm rows : straight float4 copy ---
    const float4* gW4 = (const float4*)g_Wpad_atm
                      + (size_t)(t * LMAX + m_begin) * (DV * LPAD / 4);
    float4* sW4 = (float4*)sW;
    const int n4 = m_count * (DV * LPAD / 4);    // m_count * 224
    for (int idx = tid; idx < n4; idx += TPB) sW4[idx] = gW4[idx];

    // --- stage diffs (all L columns), layout [b][d][LPAD], zero-padded ---
    const int nd = B * 3 * LPAD;
    for (int idx = tid; idx < nd; idx += TPB) {
        int b = idx / (3 * LPAD);
        int r = idx - b * (3 * LPAD);
        int d = r / LPAD;
        int l = r - d * LPAD;
        float val = 0.0f;
        if (l < L) {
            val = pos_atm[((size_t)b * atoms + start + l) * 3 + d]
                - pos_amn[((size_t)b * n_res + rid) * 3 + d];
        }
        sdiff[idx] = val;
    }
    __syncthreads();

    const int v = tid / 3;
    const int d = tid - v * 3;
    const u64* sW64v = (const u64*)sW + v * NP;
    const u64* sd64d = (const u64*)sdiff + d * NP;
    const u64* gWa64 = (const u64*)g_Wpad_amn + ((size_t)t * DV + v) * NP;

    const int bstride_atm = atoms * (DV * 3);
    const int bstride_amn = n_res * (DV * 3);

    float* qamn = out_amn + rid * (DV * 3) + tid;
    float* patm = out_atm + (size_t)(start + m_begin) * (DV * 3) + tid;
    const bool do_amn = (half == 0);

    switch (L) {
        case 3:  posmix_body<3,4> (sW64v, sd64d, gWa64, qamn, patm, B, bstride_amn, bstride_atm, m_count, do_amn); break;
        case 4:  posmix_body<4,4> (sW64v, sd64d, gWa64, qamn, patm, B, bstride_amn, bstride_atm, m_count, do_amn); break;
        case 5:  posmix_body<5,4> (sW64v, sd64d, gWa64, qamn, patm, B, bstride_amn, bstride_atm, m_count, do_amn); break;
        case 6:  posmix_body<6,4> (sW64v, sd64d, gWa64, qamn, patm, B, bstride_amn, bstride_atm, m_count, do_amn); break;
        case 7:  posmix_body<7,4> (sW64v, sd64d, gWa64, qamn, patm, B, bstride_amn, bstride_atm, m_count, do_amn); break;
        case 8:  posmix_body<8,4> (sW64v, sd64d, gWa64, qamn, patm, B, bstride_amn, bstride_atm, m_count, do_amn); break;
        case 9:  posmix_body<9,2> (sW64v, sd64d, gWa64, qamn, patm, B, bstride_amn, bstride_atm, m_count, do_amn); break;
        case 10: posmix_body<10,2>(sW64v, sd64d, gWa64, qamn, patm, B, bstride_amn, bstride_atm, m_count, do_amn); break;
        case 11: posmix_body<11,2>(sW64v, sd64d, gWa64, qamn, patm, B, bstride_amn, bstride_atm, m_count, do_amn); break;
        default: posmix_body<13,2>(sW64v, sd64d, gWa64, qamn, patm, B, bstride_amn, bstride_atm, m_count, do_amn); break;
    }
}

// ---------------------------------------------------------------------------
// Launch: d_out = concat(x_v_atm.ravel(), x_v_amn.ravel())
// ---------------------------------------------------------------------------
extern "C" void kernel_launch(void* const* d_in, const int* in_sizes, int n_in,
                              void* d_out, int out_size) {
    const float* pos_atm = (const float*)d_in[0];
    const float* pos_amn = (const float*)d_in[1];
    const float* W_amn   = (const float*)d_in[2];
    const float* W_atm   = (const float*)d_in[3];
    const int*   seq     = (const int*)d_in[4];

    const int n_res = in_sizes[4];                  // 2048
    const int B     = in_sizes[1] / (n_res * 3);    // 16
    const int atoms = in_sizes[0] / (B * 3);        // 15036

    float* out_atm = (float*)d_out;
    float* out_amn = out_atm + (size_t)B * atoms * DV * 3;

    const int smem_bytes = (HROWS * DV * LPAD + 16 * 3 * LPAD) * (int)sizeof(float); // 27,776B

    const int npad = (N_TYPES * LMAX * DV + N_TYPES * DV) * LPAD;   // 246,400
    const int prep_blocks = 1 + (npad + 1023) / 1024;               // scan + pad
    prep_kernel<<<prep_blocks, 1024>>>(seq, n_res, W_amn, W_atm);
    posmix_kernel<<<2 * n_res, TPB, smem_bytes>>>(pos_atm, pos_amn, seq,
                                                  out_atm, out_amn, B, n_res, atoms);
}

// round 17
// speedup vs baseline: 1.0005x; 1.0005x over previous
#include <cuda_runtime.h>
#include <cuda_bf16.h>

#define LMAX 13
#define LPAD 14
#define NP 7          // f32x2 pairs per padded row (LPAD/2)
#define N_TYPES 20
#define NRES_MAX 2048
#define DV 64
#define TPB 192       // = DV * 3
#define HROWS 7       // sW capacity in m-rows (chunked staging)

typedef unsigned long long u64;

// packed f32x2 fma: acc = w * dv + acc   (2 scalar FMAs in 1 issue slot)
#define FMA2(acc, w, dv) \
    asm("fma.rn.f32x2 %0, %1, %2, %3;" : "=l"(acc) : "l"(w), "l"(dv), "l"(acc))

// horizontal sum of a packed f32x2
__device__ __forceinline__ float hsum2(u64 v) {
    float lo, hi;
    asm("mov.b64 {%0, %1}, %2;" : "=f"(lo), "=f"(hi) : "l"(v));
    return lo + hi;
}

__constant__ int c_res_len[N_TYPES] = {3,4,5,5,6,6,6,7,7,7,7,7,8,8,8,9,10,10,11,13};
__device__ int g_starts[NRES_MAX];

// padded weights, built once per launch by prep_kernel
__device__ float g_Wpad_atm[N_TYPES * LMAX * DV * LPAD];  // [t][m][v][14], slot13=0
__device__ float g_Wpad_amn[N_TYPES * DV * LPAD];         // [t][v][14],    slot13=0

// ---------------------------------------------------------------------------
// Kernel 0: fused prep. Block 0: exclusive scan of residue lengths.
// Blocks 1..: pad W_atm / W_amn rows 13 -> 14 (zero slot 13).
// ---------------------------------------------------------------------------
__global__ __launch_bounds__(1024) void prep_kernel(
    const int* __restrict__ seq, int n_res,
    const float* __restrict__ W_amn, const float* __restrict__ W_atm)
{
    if (blockIdx.x == 0) {
        __shared__ int s[1024];
        int tid = threadIdx.x;
        int i0 = 2 * tid, i1 = 2 * tid + 1;
        int l0 = (i0 < n_res) ? c_res_len[seq[i0]] : 0;
        int l1 = (i1 < n_res) ? c_res_len[seq[i1]] : 0;
        int pair = l0 + l1;
        s[tid] = pair;
        __syncthreads();
        #pragma unroll
        for (int off = 1; off < 1024; off <<= 1) {
            int v = (tid >= off) ? s[tid - off] : 0;
            __syncthreads();
            s[tid] += v;
            __syncthreads();
        }
        int excl = s[tid] - pair;
        if (i0 < n_res) g_starts[i0] = excl;
        if (i1 < n_res) g_starts[i1] = excl + l0;
    } else {
        const int NATM = N_TYPES * LMAX * DV;
        const int NAMN = N_TYPES * DV;
        int idx = (blockIdx.x - 1) * 1024 + threadIdx.x;
        if (idx < NATM * LPAD) {
            int row = idx / LPAD, l = idx - row * LPAD;
            g_Wpad_atm[idx] = (l < LMAX) ? W_atm[row * LMAX + l] : 0.0f;
        } else {
            int j = idx - NATM * LPAD;
            if (j < NAMN * LPAD) {
                int row = j / LPAD, l = j - row * LPAD;
                g_Wpad_amn[j] = (l < LMAX) ? W_amn[row * LMAX + l] : 0.0f;
            }
        }
    }
}

// ---------------------------------------------------------------------------
// Hot loop for one staged chunk of m-rows. L compile-time; BB = batch-block
// factor (4 for NPL<=4, 2 for bigger, to stay within the 64-reg budget).
// ---------------------------------------------------------------------------
template<int L, int BB>
__device__ __forceinline__ void posmix_body(
    const u64* __restrict__ sW64v,     // shared W base for this thread's v
    const u64* __restrict__ sd64d,     // shared diff base for this thread's d
    const u64* __restrict__ gWa64,     // padded W_amn row for (t, v)
    float* __restrict__ qamn,
    float* __restrict__ patm,
    int B, int bstride_amn, int bstride_atm,
    int m_count, bool do_amn)
{
    constexpr int NPL = (L + 1) / 2;   // f32x2 pairs covering L (diff zero-padded)

    #pragma unroll 1
    for (int bb0 = 0; bb0 < B; bb0 += BB) {
        u64 dv[BB][NPL];
        #pragma unroll
        for (int b = 0; b < BB; b++)
            #pragma unroll
            for (int p = 0; p < NPL; p++)
                dv[b][p] = sd64d[(bb0 + b) * 3 * NP + p];

        // ---- x_v_amn (first chunk only) ----
        if (do_amn) {
            u64 c[BB];
            #pragma unroll
            for (int b = 0; b < BB; b++) c[b] = 0;
            #pragma unroll
            for (int p = 0; p < NPL; p++) {
                u64 w = gWa64[p];
                #pragma unroll
                for (int b = 0; b < BB; b++) FMA2(c[b], w, dv[b][p]);
            }
            #pragma unroll
            for (int b = 0; b < BB; b++)
                qamn[(size_t)(bb0 + b) * bstride_amn] = hsum2(c[b]);
        }

        // ---- x_v_atm : dynamic m-loop over this chunk ----
        float* pp[BB];
        #pragma unroll
        for (int b = 0; b < BB; b++)
            pp[b] = patm + (size_t)(bb0 + b) * bstride_atm;
        const u64* wr = sW64v;
        #pragma unroll 1
        for (int m = 0; m < m_count; m++) {
            u64 c[BB];
            #pragma unroll
            for (int b = 0; b < BB; b++) c[b] = 0;
            #pragma unroll
            for (int p = 0; p < NPL; p++) {
                u64 w = wr[p];
                #pragma unroll
                for (int b = 0; b < BB; b++) FMA2(c[b], w, dv[b][p]);
            }
            #pragma unroll
            for (int b = 0; b < BB; b++) {
                pp[b][0] = hsum2(c[b]);
                pp[b] += DV * 3;
            }
            wr += DV * NP;
        }
    }
}

// ---------------------------------------------------------------------------
// Driver: chunk the m-rows through a 7-row sW buffer (small smem -> 5 CTA/SM)
// without duplicating diff staging / dv loads / amn work across blocks.
// ---------------------------------------------------------------------------
template<int L, int BB>
__device__ __forceinline__ void posmix_driver(
    float* __restrict__ sW, const float4* __restrict__ gW4,
    const u64* __restrict__ sd64d, const u64* __restrict__ gWa64,
    float* __restrict__ qamn, float* __restrict__ patm,
    int tid, int v,
    int B, int bstride_amn, int bstride_atm)
{
    float4* sW4 = (float4*)sW;
    const u64* sW64v = (const u64*)sW + v * NP;

    #pragma unroll 1
    for (int c0 = 0; c0 < L; c0 += HROWS) {
        const int rows = (L - c0 < HROWS) ? (L - c0) : HROWS;
        // stage this chunk's pre-padded W rows (contiguous float4 copy)
        const float4* src = gW4 + c0 * (DV * LPAD / 4);
        const int n4 = rows * (DV * LPAD / 4);
        for (int idx = tid; idx < n4; idx += TPB) sW4[idx] = src[idx];
        __syncthreads();

        posmix_body<L, BB>(sW64v, sd64d, gWa64, qamn,
                           patm + (size_t)c0 * (DV * 3),
                           B, bstride_amn, bstride_atm,
                           rows, c0 == 0);

        if (c0 + HROWS < L) __syncthreads();   // readers done before restage
    }
}

// ---------------------------------------------------------------------------
// Kernel 2: fused gather + dual-einsum + scatter. ONE block per residue,
// small smem via chunked W staging.
// ---------------------------------------------------------------------------
__global__ __launch_bounds__(TPB, 5) void posmix_kernel(
    const float* __restrict__ pos_atm,   // (B, atoms, 3)
    const float* __restrict__ pos_amn,   // (B, n_res, 3)
    const int*   __restrict__ seq,       // (n_res,)
    float* __restrict__ out_atm,         // (B, atoms, 64, 3)
    float* __restrict__ out_amn,         // (B, n_res, 64, 3)
    int B, int n_res, int atoms)
{
    extern __shared__ float smem[];
    float* sW    = smem;                        // HROWS*DV*LPAD = 6272 floats
    float* sdiff = smem + HROWS * DV * LPAD;    // B*3*LPAD     =  672 floats

    const int i   = blockIdx.x;
    const int tid = threadIdx.x;
    const int t   = seq[i];
    const int L   = c_res_len[t];
    const int start = g_starts[i];

    // --- stage diffs once, layout [b][d][LPAD], zero-padded in l ---
    const int nd = B * 3 * LPAD;
    for (int idx = tid; idx < nd; idx += TPB) {
        int b = idx / (3 * LPAD);
        int r = idx - b * (3 * LPAD);
        int d = r / LPAD;
        int l = r - d * LPAD;
        float val = 0.0f;
        if (l < L) {
            val = pos_atm[((size_t)b * atoms + start + l) * 3 + d]
                - pos_amn[((size_t)b * n_res + i) * 3 + d];
        }
        sdiff[idx] = val;
    }
    // NOTE: no sync here; the first chunk's staging sync in the driver covers it.

    const int v = tid / 3;
    const int d = tid - v * 3;
    const u64* sd64d = (const u64*)sdiff + d * NP;
    const u64* gWa64 = (const u64*)g_Wpad_amn + ((size_t)t * DV + v) * NP;
    const float4* gW4 = (const float4*)g_Wpad_atm + (size_t)t * (LMAX * DV * LPAD / 4);

    const int bstride_atm = atoms * (DV * 3);
    const int bstride_amn = n_res * (DV * 3);

    float* qamn = out_amn + i * (DV * 3) + tid;
    float* patm = out_atm + (size_t)start * (DV * 3) + tid;

    switch (L) {
        case 3:  posmix_driver<3,4> (sW, gW4, sd64d, gWa64, qamn, patm, tid, v, B, bstride_amn, bstride_atm); break;
        case 4:  posmix_driver<4,4> (sW, gW4, sd64d, gWa64, qamn, patm, tid, v, B, bstride_amn, bstride_atm); break;
        case 5:  posmix_driver<5,4> (sW, gW4, sd64d, gWa64, qamn, patm, tid, v, B, bstride_amn, bstride_atm); break;
        case 6:  posmix_driver<6,4> (sW, gW4, sd64d, gWa64, qamn, patm, tid, v, B, bstride_amn, bstride_atm); break;
        case 7:  posmix_driver<7,4> (sW, gW4, sd64d, gWa64, qamn, patm, tid, v, B, bstride_amn, bstride_atm); break;
        case 8:  posmix_driver<8,4> (sW, gW4, sd64d, gWa64, qamn, patm, tid, v, B, bstride_amn, bstride_atm); break;
        case 9:  posmix_driver<9,2> (sW, gW4, sd64d, gWa64, qamn, patm, tid, v, B, bstride_amn, bstride_atm); break;
        case 10: posmix_driver<10,2>(sW, gW4, sd64d, gWa64, qamn, patm, tid, v, B, bstride_amn, bstride_atm); break;
        case 11: posmix_driver<11,2>(sW, gW4, sd64d, gWa64, qamn, patm, tid, v, B, bstride_amn, bstride_atm); break;
        default: posmix_driver<13,2>(sW, gW4, sd64d, gWa64, qamn, patm, tid, v, B, bstride_amn, bstride_atm); break;
    }
}

// ---------------------------------------------------------------------------
// Launch: d_out = concat(x_v_atm.ravel(), x_v_amn.ravel())
// ---------------------------------------------------------------------------
extern "C" void kernel_launch(void* const* d_in, const int* in_sizes, int n_in,
                              void* d_out, int out_size) {
    const float* pos_atm = (const float*)d_in[0];
    const float* pos_amn = (const float*)d_in[1];
    const float* W_amn   = (const float*)d_in[2];
    const float* W_atm   = (const float*)d_in[3];
    const int*   seq     = (const int*)d_in[4];

    const int n_res = in_sizes[4];                  // 2048
    const int B     = in_sizes[1] / (n_res * 3);    // 16
    const int atoms = in_sizes[0] / (B * 3);        // 15036

    float* out_atm = (float*)d_out;
    float* out_amn = out_atm + (size_t)B * atoms * DV * 3;

    const int smem_bytes = (HROWS * DV * LPAD + 16 * 3 * LPAD) * (int)sizeof(float); // 27,776B

    const int npad = (N_TYPES * LMAX * DV + N_TYPES * DV) * LPAD;   // 246,400
    const int prep_blocks = 1 + (npad + 1023) / 1024;               // scan + pad
    prep_kernel<<<prep_blocks, 1024>>>(seq, n_res, W_amn, W_atm);
    posmix_kernel<<<n_res, TPB, smem_bytes>>>(pos_atm, pos_amn, seq,
                                              out_atm, out_amn, B, n_res, atoms);
}